// round 15
// baseline (speedup 1.0000x reference)
#include <cuda_runtime.h>
#include <cuda_fp16.h>
#include <cstdint>

#define NPOS    2048
#define CIN     256
#define COUT    256
#define BATCH   64
#define TI      4
#define KC      16
#define NCHUNK  (CIN / KC)     // 16
#define THREADS 256
#define NSLOT   4
#define WSLICE  2048           // one warp-chunk W slice (2 pos x 16 rows x 16k f32)
#define SMEM_MAIN (8 * NSLOT * WSLICE)   // 65536

// scratch: xt[ig(512)][kc(16)][pos(4)][b(64)][k(16)] f16, natural k order
__device__ __half g_xt[(NPOS / TI) * NCHUNK * TI * BATCH * KC];

static __device__ __forceinline__ uint32_t smem_u32(const void* p) {
    uint32_t a;
    asm("{ .reg .u64 t; cvta.to.shared.u64 t, %1; cvt.u32.u64 %0, t; }"
        : "=r"(a) : "l"(p));
    return a;
}

static __device__ __forceinline__ uint32_t h2pack(float lo, float hi) {
    __half2 h = __floats2half2_rn(lo, hi);
    return *reinterpret_cast<uint32_t*>(&h);
}

static __device__ __forceinline__ void mma16816(float d[4], const uint32_t a[4],
                                                const uint32_t b0, const uint32_t b1) {
    asm volatile(
        "mma.sync.aligned.m16n8k16.row.col.f32.f16.f16.f32 "
        "{%0,%1,%2,%3}, {%4,%5,%6,%7}, {%8,%9}, {%0,%1,%2,%3};"
        : "+f"(d[0]), "+f"(d[1]), "+f"(d[2]), "+f"(d[3])
        : "r"(a[0]), "r"(a[1]), "r"(a[2]), "r"(a[3]), "r"(b0), "r"(b1));
}

static __device__ __forceinline__ void cp_async16(uint32_t dst, const void* src) {
    asm volatile("cp.async.cg.shared.global [%0], [%1], 16;"
                 :: "r"(dst), "l"(src) : "memory");
}
#define CP_COMMIT() asm volatile("cp.async.commit_group;" ::: "memory")
#define CP_WAIT2()  asm volatile("cp.async.wait_group 2;" ::: "memory")

static __device__ __forceinline__ float4 lds128(uint32_t addr) {
    float4 v;
    asm volatile("ld.shared.v4.f32 {%0,%1,%2,%3}, [%4];"
                 : "=f"(v.x), "=f"(v.y), "=f"(v.z), "=f"(v.w) : "r"(addr));
    return v;
}

// ============================================================================
// Pass 1: x[b][c][i] f32 -> xt[ig][kc][pos][b][k] f16 (unchanged, r14)
// ============================================================================
__global__ __launch_bounds__(256)
void x_transpose6(const float* __restrict__ x) {
    __shared__ __align__(16) __half st[32 * 256];

    const int tid = threadIdx.x;
    const int bg  = blockIdx.x >> 8;
    const int ib  = (blockIdx.x >> 2) & 63;
    const int ch  = blockIdx.x & 3;
    const int b0  = bg * 16;
    const int i0  = ib * 32;

    for (int kc = 0; kc < 4; ++kc) {
        const int kcg = ch * 4 + kc;
#pragma unroll
        for (int j = 0; j < 4; ++j) {
            const int u  = tid + j * 256;
            const int iq = u & 7;
            const int kp = (u >> 3) & 7;
            const int bl = u >> 6;
            const float* base = x + ((size_t)((b0 + bl) * CIN + kcg * KC + 2 * kp)) * NPOS
                                  + i0 + iq * 4;
            const float4 v0 = *reinterpret_cast<const float4*>(base);
            const float4 v1 = *reinterpret_cast<const float4*>(base + NPOS);
            const int col  = bl * 16 + 2 * kp;
            const int unit = col >> 3;
            const int inr  = col & 7;
            const float a[4] = {v0.x, v0.y, v0.z, v0.w};
            const float b[4] = {v1.x, v1.y, v1.z, v1.w};
#pragma unroll
            for (int e = 0; e < 4; ++e) {
                const int i  = iq * 4 + e;
                const int pu = (unit + i + (i >> 2)) & 31;
                *reinterpret_cast<__half2*>(&st[i * 256 + pu * 8 + inr]) =
                    __floats2half2_rn(a[e], b[e]);
            }
        }
        __syncthreads();
#pragma unroll
        for (int j = 0; j < 4; ++j) {
            const int u    = tid + j * 256;
            const int il   = u >> 5;
            const int part = u & 31;
            const int gi   = i0 + il;
            const int pu   = (part + il + (il >> 2)) & 31;
            const uint4 v = *reinterpret_cast<const uint4*>(&st[il * 256 + pu * 8]);
            const size_t dst = (((size_t)(gi >> 2) * NCHUNK + kcg) * TI + (gi & 3)) * 1024
                             + bg * 256 + part * 8;
            *reinterpret_cast<uint4*>(&g_xt[dst]) = v;
        }
        __syncthreads();
    }
}

// ============================================================================
// Main GEMM: per-warp cp.async W ring (depth 3, no barriers),
// B frags LDG.64 direct from xt, f16 hi-only, fp32 acc.
// ============================================================================
__global__ __launch_bounds__(THREADS, 2)
void fc_hmma13_kernel(const float* __restrict__ W,     // [N_POS, C_OUT, C_IN]
                      const float* __restrict__ bias,  // [N_POS, C_OUT]
                      float* __restrict__ out)         // [B, C_OUT, N_POS]
{
    extern __shared__ __align__(16) char dsm[];        // 64KB: 8 warps x 4 slots x 2KB

    const int tid  = threadIdx.x;
    const int wid  = tid >> 5;               // 8 warps
    const int lane = tid & 31;

    const int ig = blockIdx.x >> 2;          // i-quad group
    const int mq = blockIdx.x & 3;           // M quarter (64 rows)
    const int i0 = ig * TI;

    const int mg = wid & 3;                  // M group (16 rows)
    const int pg = wid >> 2;                 // pos-pair group

    const int row0 = lane >> 2;

    // warp-private W ring base
    const uint32_t wring = smem_u32(dsm) + (uint32_t)(wid * (NSLOT * WSLICE));

    // per-lane cp.async sources: unit u = lane + 32v  ->  lp=u>>6, row=(u>>2)&15, c=u&3
    const float* wsrc[4];
#pragma unroll
    for (int v = 0; v < 4; ++v) {
        const int u   = lane + 32 * v;
        const int lp  = u >> 6;
        const int row = (u >> 2) & 15;
        const int c   = u & 3;
        wsrc[v] = W + ((size_t)(i0 + pg * 2 + lp) * COUT + mq * 64 + mg * 16 + row) * CIN
                    + c * 4;
    }

    // B base: xt[ig] + pos offset + lane's (b-quarter, k-quad) offset (bytes)
    const char* bbase = reinterpret_cast<const char*>(g_xt + (size_t)ig * (NCHUNK * 4096))
                      + (pg * 2) * 2048 + (lane >> 2) * 32 + (lane & 3) * 8;

    float acc[2][8][4];
#pragma unroll
    for (int p = 0; p < 2; ++p)
#pragma unroll
        for (int n = 0; n < 8; ++n)
#pragma unroll
            for (int c = 0; c < 4; ++c) acc[p][n][c] = 0.0f;

    uint32_t ah[2][4];
    uint2 B0[8], B1[8];

    // issue one chunk's W cp.asyncs (or nothing) + always commit a group
    auto cpw = [&](int kc) {
        if (kc < NCHUNK) {
            const uint32_t slot = wring + (uint32_t)((kc & (NSLOT - 1)) * WSLICE)
                                + (uint32_t)(lane * 16);
#pragma unroll
            for (int v = 0; v < 4; ++v)
                cp_async16(slot + v * 512, wsrc[v] + kc * KC);
        }
        CP_COMMIT();
    };

    // read back this lane's own 4x16B and convert to A fragments
    auto ldq_cvt = [&](int kc) {
        const uint32_t slot = wring + (uint32_t)((kc & (NSLOT - 1)) * WSLICE)
                            + (uint32_t)(lane * 16);
#pragma unroll
        for (int lp = 0; lp < 2; ++lp)
#pragma unroll
            for (int r = 0; r < 2; ++r) {
                const float4 v = lds128(slot + (uint32_t)(lp * 1024 + r * 512));
                ah[lp][r]     = h2pack(v.x, v.y);
                ah[lp][r + 2] = h2pack(v.z, v.w);
            }
    };

    auto ldg_b = [&](int kc, int lp, uint2* B) {
        const char* p = bbase + kc * 8192 + lp * 2048;
#pragma unroll
        for (int nt = 0; nt < 8; ++nt)
            B[nt] = *reinterpret_cast<const uint2*>(p + nt * 256);
    };

    auto mma_lp = [&](int lp, const uint2* B) {
#pragma unroll
        for (int nt = 0; nt < 8; ++nt)
            mma16816(acc[lp][nt], ah[lp], B[nt].x, B[nt].y);
    };

    // ---- prologue: 3 W chunks in flight, B chunk 0 direct ----
    cpw(0);
    cpw(1);
    cpw(2);
    ldg_b(0, 0, B0);
    ldg_b(0, 1, B1);

#pragma unroll
    for (int kc = 0; kc < NCHUNK; ++kc) {
        CP_WAIT2();                 // W chunk kc landed (per-thread, no barrier)
        ldq_cvt(kc);                // each lane reads back its own bytes
        cpw(kc + 3);                // refill (slot (kc+3)&3 != kc&3)
        mma_lp(0, B0);
        if (kc + 1 < NCHUNK) ldg_b(kc + 1, 0, B0);
        mma_lp(1, B1);
        if (kc + 1 < NCHUNK) ldg_b(kc + 1, 1, B1);
    }

    // ---- epilogue: pos-pair exchange (reuse ring smem), float4 stores ----
    __syncthreads();
    float2* ep = reinterpret_cast<float2*>(dsm);

#pragma unroll
    for (int half = 0; half < 2; ++half) {
        const int o = mq * 64 + mg * 16 + row0 + half * 8;
        const float bvA = bias[(size_t)(i0 + pg * 2 + 0) * COUT + o];
        const float bvB = bias[(size_t)(i0 + pg * 2 + 1) * COUT + o];

        if (pg == 0) {
#pragma unroll
            for (int nt = 0; nt < 8; ++nt)
#pragma unroll
                for (int cc = 0; cc < 2; ++cc) {
                    const int e = nt * 2 + cc;
                    float2 v;
                    v.x = acc[0][nt][half * 2 + cc] + bvA;
                    v.y = acc[1][nt][half * 2 + cc] + bvB;
                    ep[(mg * 16 + e) * 32 + lane] = v;
                }
        }
        __syncthreads();
        if (pg == 1) {
#pragma unroll
            for (int nt = 0; nt < 8; ++nt)
#pragma unroll
                for (int cc = 0; cc < 2; ++cc) {
                    const int e = nt * 2 + cc;
                    const float2 v01 = ep[(mg * 16 + e) * 32 + lane];
                    float4 v;
                    v.x = v01.x;
                    v.y = v01.y;
                    v.z = acc[0][nt][half * 2 + cc] + bvA;
                    v.w = acc[1][nt][half * 2 + cc] + bvB;
                    const int b = nt * 8 + (lane & 3) * 2 + cc;
                    *reinterpret_cast<float4*>(out + (size_t)(b * COUT + o) * NPOS + i0) = v;
                }
        }
        __syncthreads();
    }
}

extern "C" void kernel_launch(void* const* d_in, const int* in_sizes, int n_in,
                              void* d_out, int out_size) {
    const float* x    = (const float*)d_in[0];
    const float* W    = (const float*)d_in[1];
    const float* bias = (const float*)d_in[2];
    float* out        = (float*)d_out;
    (void)in_sizes; (void)n_in; (void)out_size;

    static int configured = 0;
    if (!configured) {
        cudaFuncSetAttribute(fc_hmma13_kernel,
                             cudaFuncAttributeMaxDynamicSharedMemorySize, SMEM_MAIN);
        configured = 1;
    }

    x_transpose6<<<1024, 256>>>(x);
    fc_hmma13_kernel<<<(NPOS / TI) * 4, THREADS, SMEM_MAIN>>>(W, bias, out);
}

// round 16
// speedup vs baseline: 1.2210x; 1.2210x over previous
#include <cuda_runtime.h>
#include <cuda_fp16.h>
#include <cstdint>

#define NPOS    2048
#define CIN     256
#define COUT    256
#define BATCH   64
#define TI      4
#define KC      16
#define NCHUNK  (CIN / KC)     // 16
#define THREADS 256

// scratch: xt[ig(512)][kc(16)][pos(4)][b(64)][k(16)] f16, natural k order
__device__ __half g_xt[(NPOS / TI) * NCHUNK * TI * BATCH * KC];

static __device__ __forceinline__ uint32_t h2pack(float lo, float hi) {
    __half2 h = __floats2half2_rn(lo, hi);
    return *reinterpret_cast<uint32_t*>(&h);
}

static __device__ __forceinline__ void mma16816(float d[4], const uint32_t a[4],
                                                const uint32_t b0, const uint32_t b1) {
    asm volatile(
        "mma.sync.aligned.m16n8k16.row.col.f32.f16.f16.f32 "
        "{%0,%1,%2,%3}, {%4,%5,%6,%7}, {%8,%9}, {%0,%1,%2,%3};"
        : "+f"(d[0]), "+f"(d[1]), "+f"(d[2]), "+f"(d[3])
        : "r"(a[0]), "r"(a[1]), "r"(a[2]), "r"(a[3]), "r"(b0), "r"(b1));
}

// ============================================================================
// Pass 1: x[b][c][i] f32 -> xt[ig][kc][pos][b][k] f16 (unchanged, r14)
// ============================================================================
__global__ __launch_bounds__(256)
void x_transpose6(const float* __restrict__ x) {
    __shared__ __align__(16) __half st[32 * 256];

    const int tid = threadIdx.x;
    const int bg  = blockIdx.x >> 8;
    const int ib  = (blockIdx.x >> 2) & 63;
    const int ch  = blockIdx.x & 3;
    const int b0  = bg * 16;
    const int i0  = ib * 32;

    for (int kc = 0; kc < 4; ++kc) {
        const int kcg = ch * 4 + kc;
#pragma unroll
        for (int j = 0; j < 4; ++j) {
            const int u  = tid + j * 256;
            const int iq = u & 7;
            const int kp = (u >> 3) & 7;
            const int bl = u >> 6;
            const float* base = x + ((size_t)((b0 + bl) * CIN + kcg * KC + 2 * kp)) * NPOS
                                  + i0 + iq * 4;
            const float4 v0 = *reinterpret_cast<const float4*>(base);
            const float4 v1 = *reinterpret_cast<const float4*>(base + NPOS);
            const int col  = bl * 16 + 2 * kp;
            const int unit = col >> 3;
            const int inr  = col & 7;
            const float a[4] = {v0.x, v0.y, v0.z, v0.w};
            const float b[4] = {v1.x, v1.y, v1.z, v1.w};
#pragma unroll
            for (int e = 0; e < 4; ++e) {
                const int i  = iq * 4 + e;
                const int pu = (unit + i + (i >> 2)) & 31;
                *reinterpret_cast<__half2*>(&st[i * 256 + pu * 8 + inr]) =
                    __floats2half2_rn(a[e], b[e]);
            }
        }
        __syncthreads();
#pragma unroll
        for (int j = 0; j < 4; ++j) {
            const int u    = tid + j * 256;
            const int il   = u >> 5;
            const int part = u & 31;
            const int gi   = i0 + il;
            const int pu   = (part + il + (il >> 2)) & 31;
            const uint4 v = *reinterpret_cast<const uint4*>(&st[il * 256 + pu * 8]);
            const size_t dst = (((size_t)(gi >> 2) * NCHUNK + kcg) * TI + (gi & 3)) * 1024
                             + bg * 256 + part * 8;
            *reinterpret_cast<uint4*>(&g_xt[dst]) = v;
        }
        __syncthreads();
    }
}

// ============================================================================
// Main GEMM: r14 zero-barrier mainloop + symmetric split epilogue.
// ============================================================================
__global__ __launch_bounds__(THREADS, 2)
void fc_hmma14_kernel(const float* __restrict__ W,     // [N_POS, C_OUT, C_IN]
                      const float* __restrict__ bias,  // [N_POS, C_OUT]
                      float* __restrict__ out)         // [B, C_OUT, N_POS]
{
    // two exchange regions: epA = pg1's half0 values, epB = pg0's half1 values
    __shared__ __align__(16) float2 epA[4 * 16 * 32];   // 16 KB
    __shared__ __align__(16) float2 epB[4 * 16 * 32];   // 16 KB

    const int tid  = threadIdx.x;
    const int wid  = tid >> 5;               // 8 warps
    const int lane = tid & 31;

    const int ig = blockIdx.x >> 2;          // i-quad group
    const int mq = blockIdx.x & 3;           // M quarter (64 rows)
    const int i0 = ig * TI;

    const int mg = wid & 3;                  // M group (16 rows)
    const int pg = wid >> 2;                 // pos-pair group

    const int row0 = lane >> 2;
    const int kq   = (lane & 3) * 4;

    const float* Wp[2];
#pragma unroll
    for (int lp = 0; lp < 2; ++lp)
        Wp[lp] = W + ((size_t)(i0 + pg * 2 + lp) * COUT + mq * 64 + mg * 16 + row0) * CIN;

    // B base: xt[ig] + pos offset + lane's (b-quarter, k-quad) offset (bytes)
    const char* bbase = reinterpret_cast<const char*>(g_xt + (size_t)ig * (NCHUNK * 4096))
                      + (pg * 2) * 2048 + (lane >> 2) * 32 + (lane & 3) * 8;

    float acc[2][8][4];
#pragma unroll
    for (int p = 0; p < 2; ++p)
#pragma unroll
        for (int n = 0; n < 8; ++n)
#pragma unroll
            for (int c = 0; c < 4; ++c) acc[p][n][c] = 0.0f;

    float4 q[2][2];
    uint32_t ah[2][4];
    uint2 B0[8], B1[8];

    auto ldg_w = [&](int kc) {
        const int kb = kc * KC + kq;
#pragma unroll
        for (int lp = 0; lp < 2; ++lp) {
            q[lp][0] = *reinterpret_cast<const float4*>(Wp[lp] + kb);
            q[lp][1] = *reinterpret_cast<const float4*>(Wp[lp] + 8 * CIN + kb);
        }
    };

    auto cvt_w = [&]() {
#pragma unroll
        for (int lp = 0; lp < 2; ++lp) {
#pragma unroll
            for (int r = 0; r < 2; ++r) {
                const float4 v = q[lp][r];
                ah[lp][r]     = h2pack(v.x, v.y);
                ah[lp][r + 2] = h2pack(v.z, v.w);
            }
        }
    };

    auto ldg_b = [&](int kc, int lp, uint2* B) {
        const char* p = bbase + kc * 8192 + lp * 2048;
#pragma unroll
        for (int nt = 0; nt < 8; ++nt)
            B[nt] = *reinterpret_cast<const uint2*>(p + nt * 256);
    };

    auto mma_lp = [&](int lp, const uint2* B) {
#pragma unroll
        for (int nt = 0; nt < 8; ++nt)
            mma16816(acc[lp][nt], ah[lp], B[nt].x, B[nt].y);
    };

    // ---- prologue ----
    ldg_w(0);
    ldg_b(0, 0, B0);
    ldg_b(0, 1, B1);

#pragma unroll
    for (int kc = 0; kc < NCHUNK; ++kc) {
        cvt_w();
        if (kc + 1 < NCHUNK) ldg_w(kc + 1);
        mma_lp(0, B0);
        if (kc + 1 < NCHUNK) ldg_b(kc + 1, 0, B0);
        mma_lp(1, B1);
        if (kc + 1 < NCHUNK) ldg_b(kc + 1, 1, B1);
    }

    // ---- symmetric split epilogue ----
    // o_half: o(h) = mq*64 + mg*16 + row0 + h*8
    const int oH0 = mq * 64 + mg * 16 + row0;
    const int oH1 = oH0 + 8;
    // this warp's bias values for its two positions, both halves
    const float bv0A = bias[(size_t)(i0 + pg * 2 + 0) * COUT + oH0];
    const float bv0B = bias[(size_t)(i0 + pg * 2 + 1) * COUT + oH0];
    const float bv1A = bias[(size_t)(i0 + pg * 2 + 0) * COUT + oH1];
    const float bv1B = bias[(size_t)(i0 + pg * 2 + 1) * COUT + oH1];

    // STS phase: pg0 exports half1, pg1 exports half0 (bias pre-added)
    if (pg == 0) {
#pragma unroll
        for (int nt = 0; nt < 8; ++nt)
#pragma unroll
            for (int cc = 0; cc < 2; ++cc) {
                float2 v;
                v.x = acc[0][nt][2 + cc] + bv1A;
                v.y = acc[1][nt][2 + cc] + bv1B;
                epB[(mg * 16 + nt * 2 + cc) * 32 + lane] = v;
            }
    } else {
#pragma unroll
        for (int nt = 0; nt < 8; ++nt)
#pragma unroll
            for (int cc = 0; cc < 2; ++cc) {
                float2 v;
                v.x = acc[0][nt][cc] + bv0A;
                v.y = acc[1][nt][cc] + bv0B;
                epA[(mg * 16 + nt * 2 + cc) * 32 + lane] = v;
            }
    }
    __syncthreads();

    // STG phase: pg0 stores half0 outputs, pg1 stores half1 — both groups active
    if (pg == 0) {
#pragma unroll
        for (int nt = 0; nt < 8; ++nt)
#pragma unroll
            for (int cc = 0; cc < 2; ++cc) {
                const float2 v23 = epA[(mg * 16 + nt * 2 + cc) * 32 + lane];
                float4 v;
                v.x = acc[0][nt][cc] + bv0A;   // pos0
                v.y = acc[1][nt][cc] + bv0B;   // pos1
                v.z = v23.x;                   // pos2 (from pg1)
                v.w = v23.y;                   // pos3
                const int b = nt * 8 + (lane & 3) * 2 + cc;
                *reinterpret_cast<float4*>(out + (size_t)(b * COUT + oH0) * NPOS + i0) = v;
            }
    } else {
#pragma unroll
        for (int nt = 0; nt < 8; ++nt)
#pragma unroll
            for (int cc = 0; cc < 2; ++cc) {
                const float2 v01 = epB[(mg * 16 + nt * 2 + cc) * 32 + lane];
                float4 v;
                v.x = v01.x;                   // pos0 (from pg0)
                v.y = v01.y;                   // pos1
                v.z = acc[0][nt][2 + cc] + bv1A;   // pos2
                v.w = acc[1][nt][2 + cc] + bv1B;   // pos3
                const int b = nt * 8 + (lane & 3) * 2 + cc;
                *reinterpret_cast<float4*>(out + (size_t)(b * COUT + oH1) * NPOS + i0) = v;
            }
    }
}

extern "C" void kernel_launch(void* const* d_in, const int* in_sizes, int n_in,
                              void* d_out, int out_size) {
    const float* x    = (const float*)d_in[0];
    const float* W    = (const float*)d_in[1];
    const float* bias = (const float*)d_in[2];
    float* out        = (float*)d_out;
    (void)in_sizes; (void)n_in; (void)out_size;

    x_transpose6<<<1024, 256>>>(x);
    fc_hmma14_kernel<<<(NPOS / TI) * 4, THREADS>>>(W, bias, out);
}

// round 17
// speedup vs baseline: 1.2574x; 1.0298x over previous
#include <cuda_runtime.h>
#include <cuda_fp16.h>
#include <cstdint>

#define NPOS    2048
#define CIN     256
#define COUT    256
#define BATCH   64
#define TI      4
#define KC      16
#define NCHUNK  (CIN / KC)     // 16
#define THREADS 256

// scratch: xt[ig(512)][kc(16)][pos(4)][b(64)][k(16)] f16, natural k order
__device__ __half g_xt[(NPOS / TI) * NCHUNK * TI * BATCH * KC];

static __device__ __forceinline__ uint32_t h2pack(float lo, float hi) {
    __half2 h = __floats2half2_rn(lo, hi);
    return *reinterpret_cast<uint32_t*>(&h);
}

static __device__ __forceinline__ void mma16816(float d[4], const uint32_t a[4],
                                                const uint32_t b0, const uint32_t b1) {
    asm volatile(
        "mma.sync.aligned.m16n8k16.row.col.f32.f16.f16.f32 "
        "{%0,%1,%2,%3}, {%4,%5,%6,%7}, {%8,%9}, {%0,%1,%2,%3};"
        : "+f"(d[0]), "+f"(d[1]), "+f"(d[2]), "+f"(d[3])
        : "r"(a[0]), "r"(a[1]), "r"(a[2]), "r"(a[3]), "r"(b0), "r"(b1));
}

static __device__ __forceinline__ void pf_l2(const void* p) {
    asm volatile("prefetch.global.L2 [%0];" :: "l"(p));
}

// ============================================================================
// Pass 1: x[b][c][i] f32 -> xt[ig][kc][pos][b][k] f16 (unchanged, r14)
// ============================================================================
__global__ __launch_bounds__(256)
void x_transpose6(const float* __restrict__ x) {
    __shared__ __align__(16) __half st[32 * 256];

    const int tid = threadIdx.x;
    const int bg  = blockIdx.x >> 8;
    const int ib  = (blockIdx.x >> 2) & 63;
    const int ch  = blockIdx.x & 3;
    const int b0  = bg * 16;
    const int i0  = ib * 32;

    for (int kc = 0; kc < 4; ++kc) {
        const int kcg = ch * 4 + kc;
#pragma unroll
        for (int j = 0; j < 4; ++j) {
            const int u  = tid + j * 256;
            const int iq = u & 7;
            const int kp = (u >> 3) & 7;
            const int bl = u >> 6;
            const float* base = x + ((size_t)((b0 + bl) * CIN + kcg * KC + 2 * kp)) * NPOS
                                  + i0 + iq * 4;
            const float4 v0 = *reinterpret_cast<const float4*>(base);
            const float4 v1 = *reinterpret_cast<const float4*>(base + NPOS);
            const int col  = bl * 16 + 2 * kp;
            const int unit = col >> 3;
            const int inr  = col & 7;
            const float a[4] = {v0.x, v0.y, v0.z, v0.w};
            const float b[4] = {v1.x, v1.y, v1.z, v1.w};
#pragma unroll
            for (int e = 0; e < 4; ++e) {
                const int i  = iq * 4 + e;
                const int pu = (unit + i + (i >> 2)) & 31;
                *reinterpret_cast<__half2*>(&st[i * 256 + pu * 8 + inr]) =
                    __floats2half2_rn(a[e], b[e]);
            }
        }
        __syncthreads();
#pragma unroll
        for (int j = 0; j < 4; ++j) {
            const int u    = tid + j * 256;
            const int il   = u >> 5;
            const int part = u & 31;
            const int gi   = i0 + il;
            const int pu   = (part + il + (il >> 2)) & 31;
            const uint4 v = *reinterpret_cast<const uint4*>(&st[il * 256 + pu * 8]);
            const size_t dst = (((size_t)(gi >> 2) * NCHUNK + kcg) * TI + (gi & 3)) * 1024
                             + bg * 256 + part * 8;
            *reinterpret_cast<uint4*>(&g_xt[dst]) = v;
        }
        __syncthreads();
    }
}

// ============================================================================
// Main GEMM: r14 zero-barrier mainloop + L2 prefetch for W (4 ahead) and
// B/xt (3 ahead). B frags LDG.64 direct from xt, f16 hi-only, fp32 acc.
// ============================================================================
__global__ __launch_bounds__(THREADS, 2)
void fc_hmma15_kernel(const float* __restrict__ W,     // [N_POS, C_OUT, C_IN]
                      const float* __restrict__ bias,  // [N_POS, C_OUT]
                      float* __restrict__ out)         // [B, C_OUT, N_POS]
{
    __shared__ __align__(16) float2 ep[64 * 32];       // 16 KB epilogue exchange

    const int tid  = threadIdx.x;
    const int wid  = tid >> 5;               // 8 warps
    const int lane = tid & 31;

    const int ig = blockIdx.x >> 2;          // i-quad group
    const int mq = blockIdx.x & 3;           // M quarter (64 rows)
    const int i0 = ig * TI;

    const int mg = wid & 3;                  // M group (16 rows)
    const int pg = wid >> 2;                 // pos-pair group

    const int row0 = lane >> 2;
    const int kq   = (lane & 3) * 4;

    const float* Wp[2];
#pragma unroll
    for (int lp = 0; lp < 2; ++lp)
        Wp[lp] = W + ((size_t)(i0 + pg * 2 + lp) * COUT + mq * 64 + mg * 16 + row0) * CIN;

    // B base: xt[ig] + pos offset + lane's (b-quarter, k-quad) offset (bytes)
    const char* xtbase = reinterpret_cast<const char*>(g_xt + (size_t)ig * (NCHUNK * 4096));
    const char* bbase  = xtbase + (pg * 2) * 2048 + (lane >> 2) * 32 + (lane & 3) * 8;

    // prefetch lane pointers: W -> one 128B line per (lp=lane>>4, row=lane&15);
    // B -> warp's 4KB chunk region, one line per lane.
    const float* pfW = W + ((size_t)(i0 + pg * 2 + (lane >> 4)) * COUT
                            + mq * 64 + mg * 16 + (lane & 15)) * CIN;
    const char*  pfB = xtbase + pg * 4096 + lane * 128;

    float acc[2][8][4];
#pragma unroll
    for (int p = 0; p < 2; ++p)
#pragma unroll
        for (int n = 0; n < 8; ++n)
#pragma unroll
            for (int c = 0; c < 4; ++c) acc[p][n][c] = 0.0f;

    float4 q[2][2];
    uint32_t ah[2][4];
    uint2 B0[8], B1[8];

    auto ldg_w = [&](int kc) {
        const int kb = kc * KC + kq;
#pragma unroll
        for (int lp = 0; lp < 2; ++lp) {
            q[lp][0] = *reinterpret_cast<const float4*>(Wp[lp] + kb);
            q[lp][1] = *reinterpret_cast<const float4*>(Wp[lp] + 8 * CIN + kb);
        }
    };

    auto cvt_w = [&]() {
#pragma unroll
        for (int lp = 0; lp < 2; ++lp) {
#pragma unroll
            for (int r = 0; r < 2; ++r) {
                const float4 v = q[lp][r];
                ah[lp][r]     = h2pack(v.x, v.y);
                ah[lp][r + 2] = h2pack(v.z, v.w);
            }
        }
    };

    auto ldg_b = [&](int kc, int lp, uint2* B) {
        const char* p = bbase + kc * 8192 + lp * 2048;
#pragma unroll
        for (int nt = 0; nt < 8; ++nt)
            B[nt] = *reinterpret_cast<const uint2*>(p + nt * 256);
    };

    auto mma_lp = [&](int lp, const uint2* B) {
#pragma unroll
        for (int nt = 0; nt < 8; ++nt)
            mma16816(acc[lp][nt], ah[lp], B[nt].x, B[nt].y);
    };

    // ---- prologue: demand-load chunk 0, L2-prefetch chunks 1..3 ----
    pf_l2(pfW + 2 * KC);            // W lines covering chunks 2,3
    pf_l2(pfB + 1 * 8192);          // B chunk 1
    pf_l2(pfB + 2 * 8192);          // B chunk 2
    ldg_w(0);
    ldg_b(0, 0, B0);
    ldg_b(0, 1, B1);

#pragma unroll
    for (int kc = 0; kc < NCHUNK; ++kc) {
        cvt_w();
        if (kc + 1 < NCHUNK) ldg_w(kc + 1);
        // L2 prefetch ahead of the demand loads (no register cost)
        if ((kc & 1) == 0 && kc + 4 < NCHUNK) pf_l2(pfW + (kc + 4) * KC);
        if (kc + 3 < NCHUNK) pf_l2(pfB + (kc + 3) * 8192);
        mma_lp(0, B0);
        if (kc + 1 < NCHUNK) ldg_b(kc + 1, 0, B0);
        mma_lp(1, B1);
        if (kc + 1 < NCHUNK) ldg_b(kc + 1, 1, B1);
    }

    // ---- epilogue: pos-pair exchange through smem, float4 stores along i ----
    __syncthreads();

#pragma unroll
    for (int half = 0; half < 2; ++half) {
        const int o = mq * 64 + mg * 16 + row0 + half * 8;
        const float bvA = bias[(size_t)(i0 + pg * 2 + 0) * COUT + o];
        const float bvB = bias[(size_t)(i0 + pg * 2 + 1) * COUT + o];

        if (pg == 0) {
#pragma unroll
            for (int nt = 0; nt < 8; ++nt)
#pragma unroll
                for (int cc = 0; cc < 2; ++cc) {
                    const int e = nt * 2 + cc;
                    float2 v;
                    v.x = acc[0][nt][half * 2 + cc] + bvA;
                    v.y = acc[1][nt][half * 2 + cc] + bvB;
                    ep[(mg * 16 + e) * 32 + lane] = v;
                }
        }
        __syncthreads();
        if (pg == 1) {
#pragma unroll
            for (int nt = 0; nt < 8; ++nt)
#pragma unroll
                for (int cc = 0; cc < 2; ++cc) {
                    const int e = nt * 2 + cc;
                    const float2 v01 = ep[(mg * 16 + e) * 32 + lane];
                    float4 v;
                    v.x = v01.x;
                    v.y = v01.y;
                    v.z = acc[0][nt][half * 2 + cc] + bvA;
                    v.w = acc[1][nt][half * 2 + cc] + bvB;
                    const int b = nt * 8 + (lane & 3) * 2 + cc;
                    *reinterpret_cast<float4*>(out + (size_t)(b * COUT + o) * NPOS + i0) = v;
                }
        }
        __syncthreads();
    }
}

extern "C" void kernel_launch(void* const* d_in, const int* in_sizes, int n_in,
                              void* d_out, int out_size) {
    const float* x    = (const float*)d_in[0];
    const float* W    = (const float*)d_in[1];
    const float* bias = (const float*)d_in[2];
    float* out        = (float*)d_out;
    (void)in_sizes; (void)n_in; (void)out_size;

    x_transpose6<<<1024, 256>>>(x);
    fc_hmma15_kernel<<<(NPOS / TI) * 4, THREADS>>>(W, bias, out);
}